// round 12
// baseline (speedup 1.0000x reference)
#include <cuda_runtime.h>

#define NN 16000      // nodes
#define NE 256000     // edges
#define NT 640000     // triplets
#define NBATCH 128    // graphs
#define HD 64         // hidden
#define OUTD 32
#define TS 68         // smem row stride (floats): conflict-free for float4 LDS

// ---------------- device scratch ----------------
__device__ float g_Hh[NN * HD];      // h @ W1[0:64]
__device__ float g_P[NN * HD];       // h @ W2[0:64]
__device__ float g_R1[NN * HD];      // h @ Wn1[0:64]
__device__ float g_Rr3[3 * NN * HD]; // rbf[0:N] @ W1[64:70] + b1, all layers
__device__ float g_agg[NN * HD];     // triplet scatter (only rows < N matter)
__device__ float g_Q[NN * HD];       // agg @ W2[64:128] + b2
__device__ float g_aggr[NN * HD];    // edge scatter onto nodes
__device__ float g_h[NN * HD];
__device__ int g_active[NT];
__device__ int g_cnt;
__device__ float g_pool[NBATCH * HD];
__device__ float g_gcnt[NBATCH];

__device__ __forceinline__ void red_add_v4(float* addr, float4 v) {
    asm volatile("red.global.add.v4.f32 [%0], {%1,%2,%3,%4};"
                 :: "l"(addr), "f"(v.x), "f"(v.y), "f"(v.z), "f"(v.w)
                 : "memory");
}

// ---------------- tiled GEMM building blocks (128-thread blocks, 8x4 micro-tiles) ----
// A tile stored transposed in smem: As[k*TS + row], 64x64
__device__ __forceinline__ void load_A_128(float* As, const float* __restrict__ A,
                                           int row0, int t) {
    int r = t >> 1;             // 0..63
    int kb = (t & 1) * 8;       // float4 index base (8 float4 = 32 floats)
    const float4* src = (const float4*)(A + (row0 + r) * HD) + kb;
#pragma unroll
    for (int i = 0; i < 8; i++) {
        float4 v = src[i];
        int k = (kb + i) * 4;
        As[(k + 0) * TS + r] = v.x;
        As[(k + 1) * TS + r] = v.y;
        As[(k + 2) * TS + r] = v.z;
        As[(k + 3) * TS + r] = v.w;
    }
}

// W stored as Ws[k*TS + n]
__device__ __forceinline__ void load_W_128(float* Ws, const float* __restrict__ W, int t) {
    int k = t >> 1;
    int nb = (t & 1) * 8;
    const float4* src = (const float4*)(W + k * HD) + nb;
    float4* dst = (float4*)(Ws + k * TS) + nb;
#pragma unroll
    for (int i = 0; i < 8; i++) dst[i] = src[i];
}

// 8 rows x 4 cols per thread: rows ri*8..+7, cols ci*4..+3
__device__ __forceinline__ void mm64_84(const float* As, const float* Ws,
                                        float4 c[8], int ri, int ci) {
#pragma unroll 4
    for (int k = 0; k < 64; k++) {
        float4 a0 = *(const float4*)(As + k * TS + ri * 8);
        float4 a1 = *(const float4*)(As + k * TS + ri * 8 + 4);
        float4 b  = *(const float4*)(Ws + k * TS + ci * 4);
        c[0].x = fmaf(a0.x, b.x, c[0].x); c[0].y = fmaf(a0.x, b.y, c[0].y);
        c[0].z = fmaf(a0.x, b.z, c[0].z); c[0].w = fmaf(a0.x, b.w, c[0].w);
        c[1].x = fmaf(a0.y, b.x, c[1].x); c[1].y = fmaf(a0.y, b.y, c[1].y);
        c[1].z = fmaf(a0.y, b.z, c[1].z); c[1].w = fmaf(a0.y, b.w, c[1].w);
        c[2].x = fmaf(a0.z, b.x, c[2].x); c[2].y = fmaf(a0.z, b.y, c[2].y);
        c[2].z = fmaf(a0.z, b.z, c[2].z); c[2].w = fmaf(a0.z, b.w, c[2].w);
        c[3].x = fmaf(a0.w, b.x, c[3].x); c[3].y = fmaf(a0.w, b.y, c[3].y);
        c[3].z = fmaf(a0.w, b.z, c[3].z); c[3].w = fmaf(a0.w, b.w, c[3].w);
        c[4].x = fmaf(a1.x, b.x, c[4].x); c[4].y = fmaf(a1.x, b.y, c[4].y);
        c[4].z = fmaf(a1.x, b.z, c[4].z); c[4].w = fmaf(a1.x, b.w, c[4].w);
        c[5].x = fmaf(a1.y, b.x, c[5].x); c[5].y = fmaf(a1.y, b.y, c[5].y);
        c[5].z = fmaf(a1.y, b.z, c[5].z); c[5].w = fmaf(a1.y, b.w, c[5].w);
        c[6].x = fmaf(a1.z, b.x, c[6].x); c[6].y = fmaf(a1.z, b.y, c[6].y);
        c[6].z = fmaf(a1.z, b.z, c[6].z); c[6].w = fmaf(a1.z, b.w, c[6].w);
        c[7].x = fmaf(a1.w, b.x, c[7].x); c[7].y = fmaf(a1.w, b.y, c[7].y);
        c[7].z = fmaf(a1.w, b.z, c[7].z); c[7].w = fmaf(a1.w, b.w, c[7].w);
    }
}

// write micro-tile back into As transposed for a chained GEMM
__device__ __forceinline__ void store_A_trans_84(float* As, const float4 c[8], int ri, int ci) {
#pragma unroll
    for (int i = 0; i < 8; i++) {
        int r = ri * 8 + i;
        As[(ci * 4 + 0) * TS + r] = c[i].x;
        As[(ci * 4 + 1) * TS + r] = c[i].y;
        As[(ci * 4 + 2) * TS + r] = c[i].z;
        As[(ci * 4 + 3) * TS + r] = c[i].w;
    }
}

// ---------------- setup ----------------
__global__ void zero_init_kernel() {
    int i = blockIdx.x * blockDim.x + threadIdx.x;
    if (i < NN * HD / 4) ((float4*)g_agg)[i] = make_float4(0.f, 0.f, 0.f, 0.f);
    if (i < NBATCH * HD) g_pool[i] = 0.f;
    if (i < NBATCH) g_gcnt[i] = 0.f;
    if (i == 0) g_cnt = 0;
}

__global__ void compact_kernel(const int* __restrict__ j_idx) {
    int i = blockIdx.x * blockDim.x + threadIdx.x;
    if (i < NT && j_idx[i] < NN) {
        g_active[atomicAdd(&g_cnt, 1)] = i;
    }
}

// ---------------- Rr for all 3 layers in one launch ----------------
__global__ void rbfproj_all_kernel(const float* __restrict__ rbf,
                                   const float* __restrict__ W1,
                                   const float* __restrict__ b1) {
    __shared__ float Wc[6 * HD];
    __shared__ float bs[HD];
    int l = blockIdx.y;
    int t = threadIdx.x;
    const float* W = W1 + l * 76 * HD + 64 * HD;
    for (int i = t; i < 6 * HD / 4; i += blockDim.x)
        ((float4*)Wc)[i] = ((const float4*)W)[i];
    if (t < HD) bs[t] = b1[l * HD + t];
    __syncthreads();
    int node = blockIdx.x * 16 + (t >> 4);
    int c4 = t & 15;
    if (node >= NN) return;
    float4 acc = ((float4*)bs)[c4];
    const float* r = rbf + node * 6;
#pragma unroll
    for (int k = 0; k < 6; k++) {
        float v = r[k];
        float4 w = ((float4*)(Wc + k * HD))[c4];
        acc.x = fmaf(v, w.x, acc.x);
        acc.y = fmaf(v, w.y, acc.y);
        acc.z = fmaf(v, w.z, acc.z);
        acc.w = fmaf(v, w.w, acc.w);
    }
    ((float4*)(g_Rr3 + l * NN * HD + node * HD))[c4] = acc;
}

// ---------------- 3-way projection, one GEMM per block (grid (250, 3), 128 thr) ------
// use_x=1: input = x (layer 0); else input = g_h
__global__ void proj3_kernel(const float* __restrict__ x,
                             const float* __restrict__ Wa,
                             const float* __restrict__ Wb,
                             const float* __restrict__ Wc, int use_x) {
    __shared__ float As[64 * TS];
    __shared__ float Ws[64 * TS];
    int t = threadIdx.x;
    int s = blockIdx.y;
    int row0 = blockIdx.x * 64;
    const float* in = use_x ? x : g_h;
    const float* W = (s == 0) ? Wa : (s == 1) ? Wb : Wc;
    float* out = (s == 0) ? g_Hh : (s == 1) ? g_P : g_R1;
    load_A_128(As, in, row0, t);
    load_W_128(Ws, W, t);
    __syncthreads();
    int ri = t >> 4, ci = t & 15;
    float4 c[8];
#pragma unroll
    for (int i = 0; i < 8; i++) c[i] = make_float4(0.f, 0.f, 0.f, 0.f);
    mm64_84(As, Ws, c, ri, ci);
#pragma unroll
    for (int i = 0; i < 8; i++)
        *(float4*)(out + (row0 + ri * 8 + i) * HD + ci * 4) = c[i];
}

// ---------------- Q = agg @ W2b + b2 ; self-zero g_agg; zero g_aggr rows ----------------
__global__ void qproj_kernel(const float* __restrict__ W, const float* __restrict__ bias) {
    __shared__ float As[64 * TS];
    __shared__ float Ws[64 * TS];
    __shared__ float bs[HD];
    int t = threadIdx.x;
    int row0 = blockIdx.x * 64;
    load_A_128(As, g_agg, row0, t);
    // re-zero exactly the elements this thread just loaded (no cross-thread hazard),
    // and zero this block's g_aggr rows before edge_kernel runs
    {
        int r = t >> 1;
        int kb = (t & 1) * 8;
        float4 z = make_float4(0.f, 0.f, 0.f, 0.f);
        float4* dst = (float4*)(g_agg + (row0 + r) * HD) + kb;
        float4* dst2 = (float4*)(g_aggr + (row0 + r) * HD) + kb;
#pragma unroll
        for (int i = 0; i < 8; i++) { dst[i] = z; dst2[i] = z; }
    }
    load_W_128(Ws, W, t);
    if (t < HD) bs[t] = bias[t];
    __syncthreads();
    int ri = t >> 4, ci = t & 15;
    float4 bv = *(float4*)(bs + ci * 4);
    float4 c[8];
#pragma unroll
    for (int i = 0; i < 8; i++) c[i] = bv;
    mm64_84(As, Ws, c, ri, ci);
#pragma unroll
    for (int i = 0; i < 8; i++)
        *(float4*)(g_Q + (row0 + ri * 8 + i) * HD + ci * 4) = c[i];
}

// ---------------- fused node update: z -> h (chained in smem), 128 thr ----------------
__global__ void node_update_kernel(const float* __restrict__ Wn1b, const float* __restrict__ bn1,
                                   const float* __restrict__ Wn2, const float* __restrict__ bn2) {
    __shared__ float As[64 * TS];
    __shared__ float Ws[64 * TS];
    __shared__ float bs[HD];
    int t = threadIdx.x;
    int row0 = blockIdx.x * 64;
    int ri = t >> 4, ci = t & 15;

    // GEMM1: z = relu(R1 + aggr @ Wn1b + bn1)
    load_A_128(As, g_aggr, row0, t);
    load_W_128(Ws, Wn1b, t);
    if (t < HD) bs[t] = bn1[t];
    __syncthreads();
    float4 bv = *(float4*)(bs + ci * 4);
    float4 c[8];
#pragma unroll
    for (int i = 0; i < 8; i++) c[i] = bv;
    mm64_84(As, Ws, c, ri, ci);
#pragma unroll
    for (int i = 0; i < 8; i++) {
        float4 r = *(const float4*)(g_R1 + (row0 + ri * 8 + i) * HD + ci * 4);
        c[i].x = fmaxf(c[i].x + r.x, 0.f);
        c[i].y = fmaxf(c[i].y + r.y, 0.f);
        c[i].z = fmaxf(c[i].z + r.z, 0.f);
        c[i].w = fmaxf(c[i].w + r.w, 0.f);
    }
    __syncthreads();                   // all reads of As/Ws done
    store_A_trans_84(As, c, ri, ci);   // As = z
    load_W_128(Ws, Wn2, t);
    if (t < HD) bs[t] = bn2[t];
    __syncthreads();

    // GEMM2: h = z @ Wn2 + bn2
    bv = *(float4*)(bs + ci * 4);
#pragma unroll
    for (int i = 0; i < 8; i++) c[i] = bv;
    mm64_84(As, Ws, c, ri, ci);
#pragma unroll
    for (int i = 0; i < 8; i++)
        *(float4*)(g_h + (row0 + ri * 8 + i) * HD + ci * 4) = c[i];
}

// ---------------- triplet stage: only active (j_idx < N) triplets ----------------
__global__ void triplet_kernel(const float* __restrict__ cbf,
                               const int* __restrict__ k_idx,
                               const int* __restrict__ j_idx,
                               const float* __restrict__ W1, int l) {
    __shared__ float Wc[6 * HD];
    int t = threadIdx.x;
    const float* W1c = W1 + l * 76 * HD + 70 * HD;
    for (int i = t; i < 6 * HD / 4; i += blockDim.x)
        ((float4*)Wc)[i] = ((const float4*)W1c)[i];
    __syncthreads();

    const float* Rr = g_Rr3 + l * NN * HD;
    int cnt = g_cnt;
    int lane = t & 15;
    int group = (blockIdx.x * blockDim.x + t) >> 4;
    int ngroups = (gridDim.x * blockDim.x) >> 4;
    for (int i = group; i < cnt; i += ngroups) {
        int tr = g_active[i];
        int k = k_idx[tr];
        int j = j_idx[tr];
        float4 a = ((const float4*)(g_Hh + k * HD))[lane];
        float4 b = ((const float4*)(Rr + j * HD))[lane];
        a.x += b.x; a.y += b.y; a.z += b.z; a.w += b.w;
        const float* cb = cbf + tr * 6;
#pragma unroll
        for (int kk = 0; kk < 6; kk++) {
            float v = cb[kk];
            float4 w = ((const float4*)(Wc + kk * HD))[lane];
            a.x = fmaf(v, w.x, a.x);
            a.y = fmaf(v, w.y, a.y);
            a.z = fmaf(v, w.z, a.z);
            a.w = fmaf(v, w.w, a.w);
        }
        a.x = fmaxf(a.x, 0.f); a.y = fmaxf(a.y, 0.f);
        a.z = fmaxf(a.z, 0.f); a.w = fmaxf(a.w, 0.f);
        red_add_v4(g_agg + j * HD + lane * 4, a);
    }
}

// ---------------- edge stage: fi = relu(P[src]+Q[dst]); scatter into aggr[dst] ----------------
__global__ void edge_kernel(const int* __restrict__ ei) {
    int t = blockIdx.x * blockDim.x + threadIdx.x;
    int lane = t & 15;
    int group = t >> 4;
    int ngroups = (gridDim.x * blockDim.x) >> 4;
    for (int e = group; e < NE; e += ngroups) {
        int s = ei[e];
        int d = ei[NE + e];
        float4 a = ((const float4*)(g_P + s * HD))[lane];
        float4 b = ((const float4*)(g_Q + d * HD))[lane];
        a.x = fmaxf(a.x + b.x, 0.f);
        a.y = fmaxf(a.y + b.y, 0.f);
        a.z = fmaxf(a.z + b.z, 0.f);
        a.w = fmaxf(a.w + b.w, 0.f);
        red_add_v4(g_aggr + d * HD + lane * 4, a);
    }
}

// ---------------- pooling ----------------
__global__ void pool_kernel(const int* __restrict__ batch) {
    int t = blockIdx.x * blockDim.x + threadIdx.x;
    int lane = t & 15;
    int n = t >> 4;
    if (n >= NN) return;
    int b = batch[n];
    float4 v = ((const float4*)(g_h + n * HD))[lane];
    red_add_v4(g_pool + b * HD + lane * 4, v);
    if (lane == 0) atomicAdd(&g_gcnt[b], 1.0f);
}

// ---------------- final small MLP ----------------
__global__ void final_kernel(const float* __restrict__ Wo1,
                             const float* __restrict__ bo1,
                             const float* __restrict__ Wo2,
                             const float* __restrict__ bo2,
                             float* __restrict__ out) {
    __shared__ float pooled[HD];
    __shared__ float t1[HD];
    int b = blockIdx.x;
    int t = threadIdx.x;  // 64 threads
    float cnt = fmaxf(g_gcnt[b], 1.0f);
    pooled[t] = fmaxf(g_pool[b * HD + t] / cnt, 0.f);
    __syncthreads();
    float acc = bo1[t];
#pragma unroll 8
    for (int k = 0; k < HD; k++) acc = fmaf(pooled[k], Wo1[k * HD + t], acc);
    t1[t] = fmaxf(acc, 0.f);
    __syncthreads();
    if (t < OUTD) {
        float a2 = bo2[t];
#pragma unroll 8
        for (int k = 0; k < HD; k++) a2 = fmaf(t1[k], Wo2[k * OUTD + t], a2);
        out[b * OUTD + t] = a2;
    }
}

// ---------------- host orchestration ----------------
extern "C" void kernel_launch(void* const* d_in, const int* in_sizes, int n_in,
                              void* d_out, int out_size) {
    (void)in_sizes; (void)n_in; (void)out_size;
    const float* x   = (const float*)d_in[0];
    const float* rbf = (const float*)d_in[1];
    const float* cbf = (const float*)d_in[2];
    const float* W1  = (const float*)d_in[3];
    const float* b1  = (const float*)d_in[4];
    const float* W2  = (const float*)d_in[5];
    const float* b2  = (const float*)d_in[6];
    const float* Wn1 = (const float*)d_in[7];
    const float* bn1 = (const float*)d_in[8];
    const float* Wn2 = (const float*)d_in[9];
    const float* bn2 = (const float*)d_in[10];
    const float* Wo1 = (const float*)d_in[11];
    const float* bo1 = (const float*)d_in[12];
    const float* Wo2 = (const float*)d_in[13];
    const float* bo2 = (const float*)d_in[14];
    const int* ei    = (const int*)d_in[15];
    const int* k_idx = (const int*)d_in[16];
    const int* j_idx = (const int*)d_in[17];
    const int* batch = (const int*)d_in[18];
    float* out = (float*)d_out;

    zero_init_kernel<<<(NN * HD / 4 + 255) / 256, 256>>>();
    compact_kernel<<<(NT + 255) / 256, 256>>>(j_idx);
    rbfproj_all_kernel<<<dim3(NN / 16, 3), 256>>>(rbf, W1, b1);
    proj3_kernel<<<dim3(NN / 64, 3), 128>>>(x, W1, W2, Wn1, 1);

    for (int l = 0; l < 3; l++) {
        triplet_kernel<<<1024, 256>>>(cbf, k_idx, j_idx, W1, l);
        qproj_kernel<<<NN / 64, 128>>>(W2 + l * 128 * HD + 64 * HD, b2 + l * HD);
        edge_kernel<<<4096, 256>>>(ei);
        node_update_kernel<<<NN / 64, 128>>>(
            Wn1 + l * 128 * HD + 64 * HD, bn1 + l * HD,
            Wn2 + l * 64 * HD, bn2 + l * HD);
        if (l < 2) {
            int nl = l + 1;
            proj3_kernel<<<dim3(NN / 64, 3), 128>>>(
                x, W1 + nl * 76 * HD, W2 + nl * 128 * HD, Wn1 + nl * 128 * HD, 0);
        }
    }

    pool_kernel<<<(NN * 16 + 255) / 256, 256>>>(batch);
    final_kernel<<<NBATCH, 64>>>(Wo1, bo1, Wo2, bo2, out);
}

// round 16
// speedup vs baseline: 1.1741x; 1.1741x over previous
#include <cuda_runtime.h>
#include <cuda_bf16.h>
#include <stdint.h>

#define NN 16000      // nodes
#define NE 256000     // edges
#define NT 640000     // triplets
#define NBATCH 128    // graphs
#define HD 64         // hidden
#define OUTD 32
#define TS 68         // smem row stride (floats): conflict-free for float4 LDS

// ---------------- device scratch ----------------
__device__ float g_Hh[NN * HD];      // h @ W1[0:64]
__device__ float g_P[NN * HD];       // h @ W2[0:64]
__device__ float g_R1[NN * HD];      // h @ Wn1[0:64]
__device__ float g_Rr3[3 * NN * HD]; // rbf[0:N] @ W1[64:70] + b1, all layers
__device__ float g_agg[NN * HD];     // triplet scatter (only rows < N matter)
__device__ float g_Q[NN * HD];       // agg @ W2[64:128] + b2
__device__ float g_aggr[NN * HD];    // edge scatter onto nodes
__device__ float g_h[NN * HD];
__device__ int g_active[NT];
__device__ int g_cnt;
__device__ float g_pool[NBATCH * HD];
__device__ float g_gcnt[NBATCH];
// transposed bf16 hi/lo weights for the 9 projection GEMMs: [m][n][k-pair] u32
__device__ unsigned int g_Wth[9 * 2048];
__device__ unsigned int g_Wtl[9 * 2048];

__device__ __forceinline__ void red_add_v4(float* addr, float4 v) {
    asm volatile("red.global.add.v4.f32 [%0], {%1,%2,%3,%4};"
                 :: "l"(addr), "f"(v.x), "f"(v.y), "f"(v.z), "f"(v.w)
                 : "memory");
}

__device__ __forceinline__ uint32_t smem_u32(const void* p) {
    uint32_t a;
    asm("{ .reg .u64 t; cvta.to.shared.u64 t, %1; cvt.u32.u64 %0, t; }" : "=r"(a) : "l"(p));
    return a;
}

__device__ __forceinline__ unsigned int bf16pack(float a, float b) {
    __nv_bfloat16 ha = __float2bfloat16(a);
    __nv_bfloat16 hb = __float2bfloat16(b);
    return (unsigned int)__bfloat16_as_ushort(ha) |
           ((unsigned int)__bfloat16_as_ushort(hb) << 16);
}

// ---------------- mma.sync / ldmatrix helpers (sm_80-era, valid on sm_103) ----------
__device__ __forceinline__ void ldsm_x4(uint32_t& r0, uint32_t& r1, uint32_t& r2,
                                        uint32_t& r3, uint32_t addr) {
    asm volatile("ldmatrix.sync.aligned.m8n8.x4.shared.b16 {%0,%1,%2,%3}, [%4];"
                 : "=r"(r0), "=r"(r1), "=r"(r2), "=r"(r3) : "r"(addr));
}

__device__ __forceinline__ void ldsm_x2(uint32_t& r0, uint32_t& r1, uint32_t addr) {
    asm volatile("ldmatrix.sync.aligned.m8n8.x2.shared.b16 {%0,%1}, [%2];"
                 : "=r"(r0), "=r"(r1) : "r"(addr));
}

__device__ __forceinline__ void mma_bf16(float* c, uint32_t a0, uint32_t a1,
                                         uint32_t a2, uint32_t a3,
                                         uint32_t b0, uint32_t b1) {
    asm volatile(
        "mma.sync.aligned.m16n8k16.row.col.f32.bf16.bf16.f32 "
        "{%0,%1,%2,%3}, {%4,%5,%6,%7}, {%8,%9}, {%0,%1,%2,%3};"
        : "+f"(c[0]), "+f"(c[1]), "+f"(c[2]), "+f"(c[3])
        : "r"(a0), "r"(a1), "r"(a2), "r"(a3), "r"(b0), "r"(b1));
}

// ---------------- scalar tiled GEMM building blocks (R8-proven, 256-thr) -------------
__device__ __forceinline__ void load_A_global(float* As, const float* __restrict__ A,
                                              int row0, int t) {
    int r = t >> 2;             // 0..63
    int kb = (t & 3) * 16;      // 0,16,32,48
    const float4* src = (const float4*)(A + (row0 + r) * HD + kb);
#pragma unroll
    for (int i = 0; i < 4; i++) {
        float4 v = src[i];
        int k = kb + i * 4;
        As[(k + 0) * TS + r] = v.x;
        As[(k + 1) * TS + r] = v.y;
        As[(k + 2) * TS + r] = v.z;
        As[(k + 3) * TS + r] = v.w;
    }
}

__device__ __forceinline__ void load_W(float* Ws, const float* __restrict__ W, int t) {
    int k = t >> 2;
    int nb = (t & 3) * 16;
    const float4* src = (const float4*)(W + k * HD + nb);
    float4* dst = (float4*)(Ws + k * TS + nb);
#pragma unroll
    for (int i = 0; i < 4; i++) dst[i] = src[i];
}

__device__ __forceinline__ void mm64(const float* As, const float* Ws,
                                     float4 c[4], int ri, int ci) {
#pragma unroll 8
    for (int k = 0; k < 64; k++) {
        float4 a = *(const float4*)(As + k * TS + ri * 4);
        float4 b = *(const float4*)(Ws + k * TS + ci * 4);
        c[0].x = fmaf(a.x, b.x, c[0].x); c[0].y = fmaf(a.x, b.y, c[0].y);
        c[0].z = fmaf(a.x, b.z, c[0].z); c[0].w = fmaf(a.x, b.w, c[0].w);
        c[1].x = fmaf(a.y, b.x, c[1].x); c[1].y = fmaf(a.y, b.y, c[1].y);
        c[1].z = fmaf(a.y, b.z, c[1].z); c[1].w = fmaf(a.y, b.w, c[1].w);
        c[2].x = fmaf(a.z, b.x, c[2].x); c[2].y = fmaf(a.z, b.y, c[2].y);
        c[2].z = fmaf(a.z, b.z, c[2].z); c[2].w = fmaf(a.z, b.w, c[2].w);
        c[3].x = fmaf(a.w, b.x, c[3].x); c[3].y = fmaf(a.w, b.y, c[3].y);
        c[3].z = fmaf(a.w, b.z, c[3].z); c[3].w = fmaf(a.w, b.w, c[3].w);
    }
}

__device__ __forceinline__ void store_A_trans(float* As, const float4 c[4], int ri, int ci) {
#pragma unroll
    for (int i = 0; i < 4; i++) {
        int r = ri * 4 + i;
        As[(ci * 4 + 0) * TS + r] = c[i].x;
        As[(ci * 4 + 1) * TS + r] = c[i].y;
        As[(ci * 4 + 2) * TS + r] = c[i].z;
        As[(ci * 4 + 3) * TS + r] = c[i].w;
    }
}

// ---------------- setup ----------------
__global__ void zero_init_kernel() {
    int i = blockIdx.x * blockDim.x + threadIdx.x;
    if (i < NN * HD / 4) ((float4*)g_agg)[i] = make_float4(0.f, 0.f, 0.f, 0.f);
    if (i < NBATCH * HD) g_pool[i] = 0.f;
    if (i < NBATCH) g_gcnt[i] = 0.f;
    if (i == 0) g_cnt = 0;
}

__global__ void compact_kernel(const int* __restrict__ j_idx) {
    int i = blockIdx.x * blockDim.x + threadIdx.x;
    if (i < NT && j_idx[i] < NN) {
        g_active[atomicAdd(&g_cnt, 1)] = i;
    }
}

// ---------------- weight prep: transpose + bf16 hi/lo split for 9 proj matrices ------
// g_Wth[m][n*32 + kp] holds WT[n][2kp..2kp+1] (bf16x2): W transposed, k-contiguous rows
__global__ void prep_weights_kernel(const float* __restrict__ W1,
                                    const float* __restrict__ W2,
                                    const float* __restrict__ Wn1) {
    int m = blockIdx.x;      // 0..8
    int l = m / 3, s = m % 3;
    const float* src = (s == 0) ? (W1 + l * 76 * HD)
                     : (s == 1) ? (W2 + l * 128 * HD)
                                : (Wn1 + l * 128 * HD);
    for (int idx = threadIdx.x; idx < 2048; idx += blockDim.x) {
        int n = idx >> 5;       // output col -> WT row
        int kp = idx & 31;      // k-pair
        float a0 = src[(2 * kp) * HD + n];
        float a1 = src[(2 * kp + 1) * HD + n];
        __nv_bfloat16 h0 = __float2bfloat16(a0);
        __nv_bfloat16 h1 = __float2bfloat16(a1);
        float l0 = a0 - __bfloat162float(h0);
        float l1 = a1 - __bfloat162float(h1);
        g_Wth[m * 2048 + idx] = (unsigned int)__bfloat16_as_ushort(h0) |
                                ((unsigned int)__bfloat16_as_ushort(h1) << 16);
        g_Wtl[m * 2048 + idx] = (unsigned int)__bfloat16_as_ushort(__float2bfloat16(l0)) |
                                ((unsigned int)__bfloat16_as_ushort(__float2bfloat16(l1)) << 16);
    }
}

// ---------------- HMMA proj: out_s = in @ W_s, bf16 hi/lo split (3 mma passes) -------
// grid (125, 3) x 256 thr. CTA tile: M=128 rows, N=64, K=64. warp w: rows [w*16,+16).
__global__ void __launch_bounds__(256)
proj3_mma_kernel(const float* __restrict__ x, int use_x, int l) {
    __shared__ __align__(128) unsigned char Ahs[16384];  // 128 rows x 64 k bf16, SW128
    __shared__ __align__(128) unsigned char Als[16384];
    __shared__ __align__(128) unsigned char Whs[8192];   // 64 n-rows x 64 k bf16, SW128
    __shared__ __align__(128) unsigned char Wls[8192];

    int t = threadIdx.x;
    int warp = t >> 5, lane = t & 31;
    int row0 = blockIdx.x * 128;
    int s = blockIdx.y;
    int m = l * 3 + s;

    // ---- fill A hi/lo (each thread: 8 float4 of input) ----
    const float* Ain = use_x ? x : g_h;
    const float4* Af = (const float4*)(Ain + row0 * HD);
#pragma unroll
    for (int i = 0; i < 8; i++) {
        int j = i * 256 + t;        // float4 index in 128x16
        float4 v = Af[j];
        int row = j >> 4, k4 = j & 15;
        __nv_bfloat16 hx = __float2bfloat16(v.x), hy = __float2bfloat16(v.y);
        __nv_bfloat16 hz = __float2bfloat16(v.z), hw = __float2bfloat16(v.w);
        unsigned int hp0 = (unsigned int)__bfloat16_as_ushort(hx) |
                           ((unsigned int)__bfloat16_as_ushort(hy) << 16);
        unsigned int hp1 = (unsigned int)__bfloat16_as_ushort(hz) |
                           ((unsigned int)__bfloat16_as_ushort(hw) << 16);
        unsigned int lp0 = bf16pack(v.x - __bfloat162float(hx), v.y - __bfloat162float(hy));
        unsigned int lp1 = bf16pack(v.z - __bfloat162float(hz), v.w - __bfloat162float(hw));
        uint32_t off = (uint32_t)(row * 128 + k4 * 8);
        uint32_t swz = off ^ (((uint32_t)(row & 7)) << 4);
        *(uint2*)(Ahs + swz) = make_uint2(hp0, hp1);
        *(uint2*)(Als + swz) = make_uint2(lp0, lp1);
    }
    // ---- fill W hi/lo (each thread: 2 uint4) ----
    const uint4* wsh = (const uint4*)(g_Wth + m * 2048);
    const uint4* wsl = (const uint4*)(g_Wtl + m * 2048);
#pragma unroll
    for (int i = 0; i < 2; i++) {
        int j = i * 256 + t;        // uint4 index in 64x8
        int n = j >> 3, ch = j & 7;
        uint32_t off = (uint32_t)(n * 128 + ch * 16);
        uint32_t swz = off ^ (((uint32_t)(n & 7)) << 4);
        *(uint4*)(Whs + swz) = wsh[j];
        *(uint4*)(Wls + swz) = wsl[j];
    }
    __syncthreads();

    uint32_t ah_base = smem_u32(Ahs), al_base = smem_u32(Als);
    uint32_t wh_base = smem_u32(Whs), wl_base = smem_u32(Wls);

    float acc[8][4];
#pragma unroll
    for (int nt = 0; nt < 8; nt++)
#pragma unroll
        for (int i = 0; i < 4; i++) acc[nt][i] = 0.f;

    // A ldmatrix address (lane-dependent)
    int mi = lane >> 3, rr = lane & 7;
    int arow = warp * 16 + (mi & 1) * 8 + rr;
    int lq = lane & 15;
    int wrow_local = lq & 7;        // within n-tile
    int wch = (lq >> 3);            // 0/1 -> k halves of chunk

#pragma unroll
    for (int kc = 0; kc < 4; kc++) {
        uint32_t aoff = (uint32_t)(arow * 128 + kc * 32 + (mi >> 1) * 16);
        uint32_t aswz = aoff ^ (((uint32_t)(arow & 7)) << 4);
        uint32_t ah0, ah1, ah2, ah3, al0, al1, al2, al3;
        ldsm_x4(ah0, ah1, ah2, ah3, ah_base + aswz);
        ldsm_x4(al0, al1, al2, al3, al_base + aswz);
#pragma unroll
        for (int nt = 0; nt < 8; nt++) {
            int nrow = nt * 8 + wrow_local;
            uint32_t woff = (uint32_t)(nrow * 128 + kc * 32 + wch * 16);
            uint32_t wswz = woff ^ (((uint32_t)(nrow & 7)) << 4);
            uint32_t bh0, bh1, bl0, bl1;
            ldsm_x2(bh0, bh1, wh_base + wswz);
            mma_bf16(acc[nt], ah0, ah1, ah2, ah3, bh0, bh1);
            mma_bf16(acc[nt], al0, al1, al2, al3, bh0, bh1);
            ldsm_x2(bl0, bl1, wl_base + wswz);
            mma_bf16(acc[nt], ah0, ah1, ah2, ah3, bl0, bl1);
        }
    }

    // ---- epilogue: D fragment -> gmem ----
    float* out = (s == 0) ? g_Hh : (s == 1) ? g_P : g_R1;
    int orow = row0 + warp * 16 + (lane >> 2);
    int ocol = (lane & 3) * 2;
#pragma unroll
    for (int nt = 0; nt < 8; nt++) {
        *(float2*)(out + orow * HD + nt * 8 + ocol) = make_float2(acc[nt][0], acc[nt][1]);
        *(float2*)(out + (orow + 8) * HD + nt * 8 + ocol) = make_float2(acc[nt][2], acc[nt][3]);
    }
}

// ---------------- Rr for all 3 layers in one launch ----------------
__global__ void rbfproj_all_kernel(const float* __restrict__ rbf,
                                   const float* __restrict__ W1,
                                   const float* __restrict__ b1) {
    __shared__ float Wc[6 * HD];
    __shared__ float bs[HD];
    int l = blockIdx.y;
    int t = threadIdx.x;
    const float* W = W1 + l * 76 * HD + 64 * HD;
    for (int i = t; i < 6 * HD / 4; i += blockDim.x)
        ((float4*)Wc)[i] = ((const float4*)W)[i];
    if (t < HD) bs[t] = b1[l * HD + t];
    __syncthreads();
    int node = blockIdx.x * 16 + (t >> 4);
    int c4 = t & 15;
    if (node >= NN) return;
    float4 acc = ((float4*)bs)[c4];
    const float* r = rbf + node * 6;
#pragma unroll
    for (int k = 0; k < 6; k++) {
        float v = r[k];
        float4 w = ((float4*)(Wc + k * HD))[c4];
        acc.x = fmaf(v, w.x, acc.x);
        acc.y = fmaf(v, w.y, acc.y);
        acc.z = fmaf(v, w.z, acc.z);
        acc.w = fmaf(v, w.w, acc.w);
    }
    ((float4*)(g_Rr3 + l * NN * HD + node * HD))[c4] = acc;
}

// ---------------- Q = agg @ W2b + b2 ; self-zero g_agg; zero g_aggr rows ----------------
__global__ void qproj_kernel(const float* __restrict__ W, const float* __restrict__ bias) {
    __shared__ float As[64 * TS];
    __shared__ float Ws[64 * TS];
    __shared__ float bs[HD];
    int t = threadIdx.x;
    int row0 = blockIdx.x * 64;
    load_A_global(As, g_agg, row0, t);
    {
        int r = t >> 2;
        int kb = (t & 3) * 16;
        float4 z = make_float4(0.f, 0.f, 0.f, 0.f);
        float4* dst = (float4*)(g_agg + (row0 + r) * HD + kb);
        float4* dst2 = (float4*)(g_aggr + (row0 + r) * HD + kb);
#pragma unroll
        for (int i = 0; i < 4; i++) { dst[i] = z; dst2[i] = z; }
    }
    load_W(Ws, W, t);
    if (t < HD) bs[t] = bias[t];
    __syncthreads();
    int ri = t >> 4, ci = t & 15;
    float4 bv = *(float4*)(bs + ci * 4);
    float4 c[4] = {bv, bv, bv, bv};
    mm64(As, Ws, c, ri, ci);
#pragma unroll
    for (int i = 0; i < 4; i++)
        *(float4*)(g_Q + (row0 + ri * 4 + i) * HD + ci * 4) = c[i];
}

// ---------------- fused node update: z -> h (chained in smem) ----------------
__global__ void node_update_kernel(const float* __restrict__ Wn1b, const float* __restrict__ bn1,
                                   const float* __restrict__ Wn2, const float* __restrict__ bn2) {
    __shared__ float As[64 * TS];
    __shared__ float Ws[64 * TS];
    __shared__ float bs[HD];
    int t = threadIdx.x;
    int row0 = blockIdx.x * 64;
    int ri = t >> 4, ci = t & 15;

    load_A_global(As, g_aggr, row0, t);
    load_W(Ws, Wn1b, t);
    if (t < HD) bs[t] = bn1[t];
    __syncthreads();
    float4 bv = *(float4*)(bs + ci * 4);
    float4 c[4] = {bv, bv, bv, bv};
    mm64(As, Ws, c, ri, ci);
#pragma unroll
    for (int i = 0; i < 4; i++) {
        float4 r = *(const float4*)(g_R1 + (row0 + ri * 4 + i) * HD + ci * 4);
        c[i].x = fmaxf(c[i].x + r.x, 0.f);
        c[i].y = fmaxf(c[i].y + r.y, 0.f);
        c[i].z = fmaxf(c[i].z + r.z, 0.f);
        c[i].w = fmaxf(c[i].w + r.w, 0.f);
    }
    __syncthreads();
    store_A_trans(As, c, ri, ci);
    load_W(Ws, Wn2, t);
    if (t < HD) bs[t] = bn2[t];
    __syncthreads();

    bv = *(float4*)(bs + ci * 4);
    c[0] = c[1] = c[2] = c[3] = bv;
    mm64(As, Ws, c, ri, ci);
#pragma unroll
    for (int i = 0; i < 4; i++)
        *(float4*)(g_h + (row0 + ri * 4 + i) * HD + ci * 4) = c[i];
}

// ---------------- triplet stage: only active (j_idx < N) triplets ----------------
__global__ void triplet_kernel(const float* __restrict__ cbf,
                               const int* __restrict__ k_idx,
                               const int* __restrict__ j_idx,
                               const float* __restrict__ W1, int l) {
    __shared__ float Wc[6 * HD];
    int t = threadIdx.x;
    const float* W1c = W1 + l * 76 * HD + 70 * HD;
    for (int i = t; i < 6 * HD / 4; i += blockDim.x)
        ((float4*)Wc)[i] = ((const float4*)W1c)[i];
    __syncthreads();

    const float* Rr = g_Rr3 + l * NN * HD;
    int cnt = g_cnt;
    int lane = t & 15;
    int group = (blockIdx.x * blockDim.x + t) >> 4;
    int ngroups = (gridDim.x * blockDim.x) >> 4;
    for (int i = group; i < cnt; i += ngroups) {
        int tr = g_active[i];
        int k = k_idx[tr];
        int j = j_idx[tr];
        float4 a = ((const float4*)(g_Hh + k * HD))[lane];
        float4 b = ((const float4*)(Rr + j * HD))[lane];
        a.x += b.x; a.y += b.y; a.z += b.z; a.w += b.w;
        const float* cb = cbf + tr * 6;
#pragma unroll
        for (int kk = 0; kk < 6; kk++) {
            float v = cb[kk];
            float4 w = ((const float4*)(Wc + kk * HD))[lane];
            a.x = fmaf(v, w.x, a.x);
            a.y = fmaf(v, w.y, a.y);
            a.z = fmaf(v, w.z, a.z);
            a.w = fmaf(v, w.w, a.w);
        }
        a.x = fmaxf(a.x, 0.f); a.y = fmaxf(a.y, 0.f);
        a.z = fmaxf(a.z, 0.f); a.w = fmaxf(a.w, 0.f);
        red_add_v4(g_agg + j * HD + lane * 4, a);
    }
}

// ---------------- edge stage: fi = relu(P[src]+Q[dst]); scatter into aggr[dst] ----------------
__global__ void edge_kernel(const int* __restrict__ ei) {
    int t = blockIdx.x * blockDim.x + threadIdx.x;
    int lane = t & 15;
    int group = t >> 4;
    int ngroups = (gridDim.x * blockDim.x) >> 4;
    for (int e = group; e < NE; e += ngroups) {
        int s = ei[e];
        int d = ei[NE + e];
        float4 a = ((const float4*)(g_P + s * HD))[lane];
        float4 b = ((const float4*)(g_Q + d * HD))[lane];
        a.x = fmaxf(a.x + b.x, 0.f);
        a.y = fmaxf(a.y + b.y, 0.f);
        a.z = fmaxf(a.z + b.z, 0.f);
        a.w = fmaxf(a.w + b.w, 0.f);
        red_add_v4(g_aggr + d * HD + lane * 4, a);
    }
}

// ---------------- pooling ----------------
__global__ void pool_kernel(const int* __restrict__ batch) {
    int t = blockIdx.x * blockDim.x + threadIdx.x;
    int lane = t & 15;
    int n = t >> 4;
    if (n >= NN) return;
    int b = batch[n];
    float4 v = ((const float4*)(g_h + n * HD))[lane];
    red_add_v4(g_pool + b * HD + lane * 4, v);
    if (lane == 0) atomicAdd(&g_gcnt[b], 1.0f);
}

// ---------------- final small MLP ----------------
__global__ void final_kernel(const float* __restrict__ Wo1,
                             const float* __restrict__ bo1,
                             const float* __restrict__ Wo2,
                             const float* __restrict__ bo2,
                             float* __restrict__ out) {
    __shared__ float pooled[HD];
    __shared__ float t1[HD];
    int b = blockIdx.x;
    int t = threadIdx.x;  // 64 threads
    float cnt = fmaxf(g_gcnt[b], 1.0f);
    pooled[t] = fmaxf(g_pool[b * HD + t] / cnt, 0.f);
    __syncthreads();
    float acc = bo1[t];
#pragma unroll 8
    for (int k = 0; k < HD; k++) acc = fmaf(pooled[k], Wo1[k * HD + t], acc);
    t1[t] = fmaxf(acc, 0.f);
    __syncthreads();
    if (t < OUTD) {
        float a2 = bo2[t];
#pragma unroll 8
        for (int k = 0; k < HD; k++) a2 = fmaf(t1[k], Wo2[k * OUTD + t], a2);
        out[b * OUTD + t] = a2;
    }
}

// ---------------- host orchestration ----------------
extern "C" void kernel_launch(void* const* d_in, const int* in_sizes, int n_in,
                              void* d_out, int out_size) {
    (void)in_sizes; (void)n_in; (void)out_size;
    const float* x   = (const float*)d_in[0];
    const float* rbf = (const float*)d_in[1];
    const float* cbf = (const float*)d_in[2];
    const float* W1  = (const float*)d_in[3];
    const float* b1  = (const float*)d_in[4];
    const float* W2  = (const float*)d_in[5];
    const float* b2  = (const float*)d_in[6];
    const float* Wn1 = (const float*)d_in[7];
    const float* bn1 = (const float*)d_in[8];
    const float* Wn2 = (const float*)d_in[9];
    const float* bn2 = (const float*)d_in[10];
    const float* Wo1 = (const float*)d_in[11];
    const float* bo1 = (const float*)d_in[12];
    const float* Wo2 = (const float*)d_in[13];
    const float* bo2 = (const float*)d_in[14];
    const int* ei    = (const int*)d_in[15];
    const int* k_idx = (const int*)d_in[16];
    const int* j_idx = (const int*)d_in[17];
    const int* batch = (const int*)d_in[18];
    float* out = (float*)d_out;

    zero_init_kernel<<<(NN * HD / 4 + 255) / 256, 256>>>();
    compact_kernel<<<(NT + 255) / 256, 256>>>(j_idx);
    prep_weights_kernel<<<9, 256>>>(W1, W2, Wn1);
    rbfproj_all_kernel<<<dim3(NN / 16, 3), 256>>>(rbf, W1, b1);
    proj3_mma_kernel<<<dim3(NN / 128, 3), 256>>>(x, 1, 0);

    for (int l = 0; l < 3; l++) {
        triplet_kernel<<<1024, 256>>>(cbf, k_idx, j_idx, W1, l);
        qproj_kernel<<<NN / 64, 256>>>(W2 + l * 128 * HD + 64 * HD, b2 + l * HD);
        edge_kernel<<<4096, 256>>>(ei);
        node_update_kernel<<<NN / 64, 256>>>(
            Wn1 + l * 128 * HD + 64 * HD, bn1 + l * HD,
            Wn2 + l * 64 * HD, bn2 + l * HD);
        if (l < 2) {
            proj3_mma_kernel<<<dim3(NN / 128, 3), 256>>>(x, 0, l + 1);
        }
    }

    pool_kernel<<<(NN * 16 + 255) / 256, 256>>>(batch);
    final_kernel<<<NBATCH, 64>>>(Wo1, bo1, Wo2, bo2, out);
}

// round 17
// speedup vs baseline: 1.3154x; 1.1204x over previous
#include <cuda_runtime.h>
#include <cuda_bf16.h>
#include <stdint.h>

#define NN 16000      // nodes
#define NE 256000     // edges
#define NT 640000     // triplets
#define NBATCH 128    // graphs
#define HD 64         // hidden
#define OUTD 32

// ---------------- device scratch ----------------
__device__ float g_Hh[NN * HD];      // h @ W1[0:64]
__device__ float g_P[NN * HD];       // h @ W2[0:64]
__device__ float g_R1[NN * HD];      // h @ Wn1[0:64]
__device__ float g_Rr3[3 * NN * HD]; // rbf[0:N] @ W1[64:70] + b1, all layers
__device__ float g_agg[NN * HD];     // triplet scatter (only rows < N matter)
__device__ float g_Q[NN * HD];       // agg @ W2[64:128] + b2
__device__ float g_aggr[NN * HD];    // edge scatter onto nodes
__device__ float g_h[NN * HD];
__device__ int g_active[NT];
__device__ int g_cnt;
__device__ float g_pool[NBATCH * HD];
__device__ float g_gcnt[NBATCH];
// transposed bf16 hi/lo weights, 18 matrices: m = l*6 + s
// s: 0=W1a 1=W2a 2=Wn1a 3=W2b 4=Wn1b 5=Wn2 ; layout [m][n*32 + kpair] u32
__device__ unsigned int g_Wth[18 * 2048];
__device__ unsigned int g_Wtl[18 * 2048];

__device__ __forceinline__ void red_add_v4(float* addr, float4 v) {
    asm volatile("red.global.add.v4.f32 [%0], {%1,%2,%3,%4};"
                 :: "l"(addr), "f"(v.x), "f"(v.y), "f"(v.z), "f"(v.w)
                 : "memory");
}

__device__ __forceinline__ uint32_t smem_u32(const void* p) {
    uint32_t a;
    asm("{ .reg .u64 t; cvta.to.shared.u64 t, %1; cvt.u32.u64 %0, t; }" : "=r"(a) : "l"(p));
    return a;
}

__device__ __forceinline__ unsigned int bf16pack(float a, float b) {
    __nv_bfloat16 ha = __float2bfloat16(a);
    __nv_bfloat16 hb = __float2bfloat16(b);
    return (unsigned int)__bfloat16_as_ushort(ha) |
           ((unsigned int)__bfloat16_as_ushort(hb) << 16);
}

// ---------------- mma.sync / ldmatrix helpers (sm_80-era, valid on sm_103) ----------
__device__ __forceinline__ void ldsm_x4(uint32_t& r0, uint32_t& r1, uint32_t& r2,
                                        uint32_t& r3, uint32_t addr) {
    asm volatile("ldmatrix.sync.aligned.m8n8.x4.shared.b16 {%0,%1,%2,%3}, [%4];"
                 : "=r"(r0), "=r"(r1), "=r"(r2), "=r"(r3) : "r"(addr));
}

__device__ __forceinline__ void ldsm_x2(uint32_t& r0, uint32_t& r1, uint32_t addr) {
    asm volatile("ldmatrix.sync.aligned.m8n8.x2.shared.b16 {%0,%1}, [%2];"
                 : "=r"(r0), "=r"(r1) : "r"(addr));
}

__device__ __forceinline__ void mma_bf16(float* c, uint32_t a0, uint32_t a1,
                                         uint32_t a2, uint32_t a3,
                                         uint32_t b0, uint32_t b1) {
    asm volatile(
        "mma.sync.aligned.m16n8k16.row.col.f32.bf16.bf16.f32 "
        "{%0,%1,%2,%3}, {%4,%5,%6,%7}, {%8,%9}, {%0,%1,%2,%3};"
        : "+f"(c[0]), "+f"(c[1]), "+f"(c[2]), "+f"(c[3])
        : "r"(a0), "r"(a1), "r"(a2), "r"(a3), "r"(b0), "r"(b1));
}

// shared tile-GEMM core: 128x64x64, bf16 hi/lo 3-pass, per-warp 16 rows
__device__ __forceinline__ void mma_tile_compute(
    uint32_t ah_base, uint32_t al_base, uint32_t wh_base, uint32_t wl_base,
    float acc[8][4], int warp, int lane) {
    int mi = lane >> 3, rr = lane & 7;
    int arow = warp * 16 + (mi & 1) * 8 + rr;
    int lq = lane & 15;
    int wrow_local = lq & 7;
    int wch = (lq >> 3);
#pragma unroll
    for (int kc = 0; kc < 4; kc++) {
        uint32_t aoff = (uint32_t)(arow * 128 + kc * 32 + (mi >> 1) * 16);
        uint32_t aswz = aoff ^ (((uint32_t)(arow & 7)) << 4);
        uint32_t ah0, ah1, ah2, ah3, al0, al1, al2, al3;
        ldsm_x4(ah0, ah1, ah2, ah3, ah_base + aswz);
        ldsm_x4(al0, al1, al2, al3, al_base + aswz);
#pragma unroll
        for (int nt = 0; nt < 8; nt++) {
            int nrow = nt * 8 + wrow_local;
            uint32_t woff = (uint32_t)(nrow * 128 + kc * 32 + wch * 16);
            uint32_t wswz = woff ^ (((uint32_t)(nrow & 7)) << 4);
            uint32_t bh0, bh1, bl0, bl1;
            ldsm_x2(bh0, bh1, wh_base + wswz);
            mma_bf16(acc[nt], ah0, ah1, ah2, ah3, bh0, bh1);
            mma_bf16(acc[nt], al0, al1, al2, al3, bh0, bh1);
            ldsm_x2(bl0, bl1, wl_base + wswz);
            mma_bf16(acc[nt], ah0, ah1, ah2, ah3, bl0, bl1);
        }
    }
}

// fill W hi/lo smem tiles from prepped tables (256 threads)
__device__ __forceinline__ void fill_W_smem(unsigned char* Whs, unsigned char* Wls,
                                            int m, int t) {
    const uint4* wsh = (const uint4*)(g_Wth + m * 2048);
    const uint4* wsl = (const uint4*)(g_Wtl + m * 2048);
#pragma unroll
    for (int i = 0; i < 2; i++) {
        int j = i * 256 + t;
        int n = j >> 3, ch = j & 7;
        uint32_t off = (uint32_t)(n * 128 + ch * 16);
        uint32_t swz = off ^ (((uint32_t)(n & 7)) << 4);
        *(uint4*)(Whs + swz) = wsh[j];
        *(uint4*)(Wls + swz) = wsl[j];
    }
}

// ---------------- setup ----------------
__global__ void zero_init_kernel() {
    int i = blockIdx.x * blockDim.x + threadIdx.x;
    if (i < NN * HD / 4) ((float4*)g_agg)[i] = make_float4(0.f, 0.f, 0.f, 0.f);
    if (i < NBATCH * HD) g_pool[i] = 0.f;
    if (i < NBATCH) g_gcnt[i] = 0.f;
    if (i == 0) g_cnt = 0;
}

__global__ void compact_kernel(const int* __restrict__ j_idx) {
    int i = blockIdx.x * blockDim.x + threadIdx.x;
    if (i < NT && j_idx[i] < NN) {
        g_active[atomicAdd(&g_cnt, 1)] = i;
    }
}

// ---------------- weight prep: transpose + bf16 hi/lo split, 18 matrices ------------
__global__ void prep_weights_kernel(const float* __restrict__ W1,
                                    const float* __restrict__ W2,
                                    const float* __restrict__ Wn1,
                                    const float* __restrict__ Wn2) {
    int m = blockIdx.x;      // 0..17
    int l = m / 6, s = m % 6;
    const float* src =
        (s == 0) ? (W1 + l * 76 * HD)
      : (s == 1) ? (W2 + l * 128 * HD)
      : (s == 2) ? (Wn1 + l * 128 * HD)
      : (s == 3) ? (W2 + l * 128 * HD + 64 * HD)
      : (s == 4) ? (Wn1 + l * 128 * HD + 64 * HD)
                 : (Wn2 + l * 64 * HD);
    for (int idx = threadIdx.x; idx < 2048; idx += blockDim.x) {
        int n = idx >> 5;       // output col -> WT row
        int kp = idx & 31;      // k-pair
        float a0 = src[(2 * kp) * HD + n];
        float a1 = src[(2 * kp + 1) * HD + n];
        __nv_bfloat16 h0 = __float2bfloat16(a0);
        __nv_bfloat16 h1 = __float2bfloat16(a1);
        float l0 = a0 - __bfloat162float(h0);
        float l1 = a1 - __bfloat162float(h1);
        g_Wth[m * 2048 + idx] = (unsigned int)__bfloat16_as_ushort(h0) |
                                ((unsigned int)__bfloat16_as_ushort(h1) << 16);
        g_Wtl[m * 2048 + idx] = (unsigned int)__bfloat16_as_ushort(__float2bfloat16(l0)) |
                                ((unsigned int)__bfloat16_as_ushort(__float2bfloat16(l1)) << 16);
    }
}

// ---------------- HMMA proj3: Hh/P/R1 = in @ {W1a,W2a,Wn1a} -------------------------
__global__ void __launch_bounds__(256)
proj3_mma_kernel(const float* __restrict__ x, int use_x, int l) {
    __shared__ __align__(128) unsigned char Ahs[16384];
    __shared__ __align__(128) unsigned char Als[16384];
    __shared__ __align__(128) unsigned char Whs[8192];
    __shared__ __align__(128) unsigned char Wls[8192];

    int t = threadIdx.x;
    int warp = t >> 5, lane = t & 31;
    int row0 = blockIdx.x * 128;
    int s = blockIdx.y;
    int m = l * 6 + s;

    const float* Ain = use_x ? x : g_h;
    const float4* Af = (const float4*)(Ain + row0 * HD);
#pragma unroll
    for (int i = 0; i < 8; i++) {
        int j = i * 256 + t;
        float4 v = Af[j];
        int row = j >> 4, k4 = j & 15;
        __nv_bfloat16 hx = __float2bfloat16(v.x), hy = __float2bfloat16(v.y);
        __nv_bfloat16 hz = __float2bfloat16(v.z), hw = __float2bfloat16(v.w);
        unsigned int hp0 = (unsigned int)__bfloat16_as_ushort(hx) |
                           ((unsigned int)__bfloat16_as_ushort(hy) << 16);
        unsigned int hp1 = (unsigned int)__bfloat16_as_ushort(hz) |
                           ((unsigned int)__bfloat16_as_ushort(hw) << 16);
        unsigned int lp0 = bf16pack(v.x - __bfloat162float(hx), v.y - __bfloat162float(hy));
        unsigned int lp1 = bf16pack(v.z - __bfloat162float(hz), v.w - __bfloat162float(hw));
        uint32_t off = (uint32_t)(row * 128 + k4 * 8);
        uint32_t swz = off ^ (((uint32_t)(row & 7)) << 4);
        *(uint2*)(Ahs + swz) = make_uint2(hp0, hp1);
        *(uint2*)(Als + swz) = make_uint2(lp0, lp1);
    }
    fill_W_smem(Whs, Wls, m, t);
    __syncthreads();

    float acc[8][4];
#pragma unroll
    for (int nt = 0; nt < 8; nt++)
#pragma unroll
        for (int i = 0; i < 4; i++) acc[nt][i] = 0.f;

    mma_tile_compute(smem_u32(Ahs), smem_u32(Als), smem_u32(Whs), smem_u32(Wls),
                     acc, warp, lane);

    float* out = (s == 0) ? g_Hh : (s == 1) ? g_P : g_R1;
    int orow = row0 + warp * 16 + (lane >> 2);
    int ocol = (lane & 3) * 2;
#pragma unroll
    for (int nt = 0; nt < 8; nt++) {
        *(float2*)(out + orow * HD + nt * 8 + ocol) = make_float2(acc[nt][0], acc[nt][1]);
        *(float2*)(out + (orow + 8) * HD + nt * 8 + ocol) = make_float2(acc[nt][2], acc[nt][3]);
    }
}

// ---------------- HMMA qproj: Q = agg @ W2b + b2 ; self-zero g_agg; zero g_aggr -----
__global__ void __launch_bounds__(256)
qproj_mma_kernel(const float* __restrict__ bias, int l) {
    __shared__ __align__(128) unsigned char Ahs[16384];
    __shared__ __align__(128) unsigned char Als[16384];
    __shared__ __align__(128) unsigned char Whs[8192];
    __shared__ __align__(128) unsigned char Wls[8192];

    int t = threadIdx.x;
    int warp = t >> 5, lane = t & 31;
    int row0 = blockIdx.x * 128;
    int m = l * 6 + 3;   // W2b

    float4* Aagg = (float4*)(g_agg + row0 * HD);
    float4* Aaggr = (float4*)(g_aggr + row0 * HD);
#pragma unroll
    for (int i = 0; i < 8; i++) {
        int j = i * 256 + t;
        float4 v = Aagg[j];
        // re-zero exactly the elements just read; also zero aggr for edge_kernel
        float4 z4 = make_float4(0.f, 0.f, 0.f, 0.f);
        Aagg[j] = z4;
        Aaggr[j] = z4;
        int row = j >> 4, k4 = j & 15;
        __nv_bfloat16 hx = __float2bfloat16(v.x), hy = __float2bfloat16(v.y);
        __nv_bfloat16 hz = __float2bfloat16(v.z), hw = __float2bfloat16(v.w);
        unsigned int hp0 = (unsigned int)__bfloat16_as_ushort(hx) |
                           ((unsigned int)__bfloat16_as_ushort(hy) << 16);
        unsigned int hp1 = (unsigned int)__bfloat16_as_ushort(hz) |
                           ((unsigned int)__bfloat16_as_ushort(hw) << 16);
        unsigned int lp0 = bf16pack(v.x - __bfloat162float(hx), v.y - __bfloat162float(hy));
        unsigned int lp1 = bf16pack(v.z - __bfloat162float(hz), v.w - __bfloat162float(hw));
        uint32_t off = (uint32_t)(row * 128 + k4 * 8);
        uint32_t swz = off ^ (((uint32_t)(row & 7)) << 4);
        *(uint2*)(Ahs + swz) = make_uint2(hp0, hp1);
        *(uint2*)(Als + swz) = make_uint2(lp0, lp1);
    }
    fill_W_smem(Whs, Wls, m, t);
    __syncthreads();

    float acc[8][4];
#pragma unroll
    for (int nt = 0; nt < 8; nt++)
#pragma unroll
        for (int i = 0; i < 4; i++) acc[nt][i] = 0.f;

    mma_tile_compute(smem_u32(Ahs), smem_u32(Als), smem_u32(Whs), smem_u32(Wls),
                     acc, warp, lane);

    int orow = row0 + warp * 16 + (lane >> 2);
    int ocol = (lane & 3) * 2;
#pragma unroll
    for (int nt = 0; nt < 8; nt++) {
        float b0 = bias[nt * 8 + ocol], b1 = bias[nt * 8 + ocol + 1];
        *(float2*)(g_Q + orow * HD + nt * 8 + ocol) =
            make_float2(acc[nt][0] + b0, acc[nt][1] + b1);
        *(float2*)(g_Q + (orow + 8) * HD + nt * 8 + ocol) =
            make_float2(acc[nt][2] + b0, acc[nt][3] + b1);
    }
}

// ---------------- HMMA node update: z = relu(R1 + aggr@Wn1b + bn1); h = z@Wn2 + bn2 -
__global__ void __launch_bounds__(256)
node_update_mma_kernel(const float* __restrict__ bn1,
                       const float* __restrict__ bn2, int l) {
    __shared__ __align__(128) unsigned char Ahs[16384];
    __shared__ __align__(128) unsigned char Als[16384];
    __shared__ __align__(128) unsigned char Whs[8192];
    __shared__ __align__(128) unsigned char Wls[8192];

    int t = threadIdx.x;
    int warp = t >> 5, lane = t & 31;
    int row0 = blockIdx.x * 128;

    // GEMM1 A = aggr
    const float4* Af = (const float4*)(g_aggr + row0 * HD);
#pragma unroll
    for (int i = 0; i < 8; i++) {
        int j = i * 256 + t;
        float4 v = Af[j];
        int row = j >> 4, k4 = j & 15;
        __nv_bfloat16 hx = __float2bfloat16(v.x), hy = __float2bfloat16(v.y);
        __nv_bfloat16 hz = __float2bfloat16(v.z), hw = __float2bfloat16(v.w);
        unsigned int hp0 = (unsigned int)__bfloat16_as_ushort(hx) |
                           ((unsigned int)__bfloat16_as_ushort(hy) << 16);
        unsigned int hp1 = (unsigned int)__bfloat16_as_ushort(hz) |
                           ((unsigned int)__bfloat16_as_ushort(hw) << 16);
        unsigned int lp0 = bf16pack(v.x - __bfloat162float(hx), v.y - __bfloat162float(hy));
        unsigned int lp1 = bf16pack(v.z - __bfloat162float(hz), v.w - __bfloat162float(hw));
        uint32_t off = (uint32_t)(row * 128 + k4 * 8);
        uint32_t swz = off ^ (((uint32_t)(row & 7)) << 4);
        *(uint2*)(Ahs + swz) = make_uint2(hp0, hp1);
        *(uint2*)(Als + swz) = make_uint2(lp0, lp1);
    }
    fill_W_smem(Whs, Wls, l * 6 + 4, t);   // Wn1b
    __syncthreads();

    float acc[8][4];
#pragma unroll
    for (int nt = 0; nt < 8; nt++)
#pragma unroll
        for (int i = 0; i < 4; i++) acc[nt][i] = 0.f;

    mma_tile_compute(smem_u32(Ahs), smem_u32(Als), smem_u32(Whs), smem_u32(Wls),
                     acc, warp, lane);
    __syncthreads();   // all warps done reading A/W smem before overwrite

    // epilogue1: z = relu(acc + R1 + bn1); repack z into A smem as bf16 hi/lo
    int orow_l = warp * 16 + (lane >> 2);       // local row in [0,128)
    int orow = row0 + orow_l;
    int ocol = (lane & 3) * 2;
#pragma unroll
    for (int nt = 0; nt < 8; nt++) {
        int col = nt * 8 + ocol;
        float b0 = bn1[col], b1 = bn1[col + 1];
        float2 r0 = *(const float2*)(g_R1 + orow * HD + col);
        float2 r1 = *(const float2*)(g_R1 + (orow + 8) * HD + col);
        float z00 = fmaxf(acc[nt][0] + r0.x + b0, 0.f);
        float z01 = fmaxf(acc[nt][1] + r0.y + b1, 0.f);
        float z10 = fmaxf(acc[nt][2] + r1.x + b0, 0.f);
        float z11 = fmaxf(acc[nt][3] + r1.y + b1, 0.f);
        // pack into A tiles at (row, k=col), bf16x2 per u32 (cols are consecutive pair)
        {
            __nv_bfloat16 h0 = __float2bfloat16(z00), h1 = __float2bfloat16(z01);
            unsigned int hp = (unsigned int)__bfloat16_as_ushort(h0) |
                              ((unsigned int)__bfloat16_as_ushort(h1) << 16);
            unsigned int lp = bf16pack(z00 - __bfloat162float(h0), z01 - __bfloat162float(h1));
            uint32_t off = (uint32_t)(orow_l * 128 + col * 2);
            uint32_t swz = off ^ (((uint32_t)(orow_l & 7)) << 4);
            *(unsigned int*)(Ahs + swz) = hp;
            *(unsigned int*)(Als + swz) = lp;
        }
        {
            int r2 = orow_l + 8;
            __nv_bfloat16 h0 = __float2bfloat16(z10), h1 = __float2bfloat16(z11);
            unsigned int hp = (unsigned int)__bfloat16_as_ushort(h0) |
                              ((unsigned int)__bfloat16_as_ushort(h1) << 16);
            unsigned int lp = bf16pack(z10 - __bfloat162float(h0), z11 - __bfloat162float(h1));
            uint32_t off = (uint32_t)(r2 * 128 + col * 2);
            uint32_t swz = off ^ (((uint32_t)(r2 & 7)) << 4);
            *(unsigned int*)(Ahs + swz) = hp;
            *(unsigned int*)(Als + swz) = lp;
        }
    }
    fill_W_smem(Whs, Wls, l * 6 + 5, t);   // Wn2
    __syncthreads();

    // GEMM2: h = z @ Wn2 + bn2
#pragma unroll
    for (int nt = 0; nt < 8; nt++)
#pragma unroll
        for (int i = 0; i < 4; i++) acc[nt][i] = 0.f;

    mma_tile_compute(smem_u32(Ahs), smem_u32(Als), smem_u32(Whs), smem_u32(Wls),
                     acc, warp, lane);

#pragma unroll
    for (int nt = 0; nt < 8; nt++) {
        int col = nt * 8 + ocol;
        float b0 = bn2[col], b1 = bn2[col + 1];
        *(float2*)(g_h + orow * HD + col) = make_float2(acc[nt][0] + b0, acc[nt][1] + b1);
        *(float2*)(g_h + (orow + 8) * HD + col) = make_float2(acc[nt][2] + b0, acc[nt][3] + b1);
    }
}

// ---------------- Rr for all 3 layers in one launch ----------------
__global__ void rbfproj_all_kernel(const float* __restrict__ rbf,
                                   const float* __restrict__ W1,
                                   const float* __restrict__ b1) {
    __shared__ float Wc[6 * HD];
    __shared__ float bs[HD];
    int l = blockIdx.y;
    int t = threadIdx.x;
    const float* W = W1 + l * 76 * HD + 64 * HD;
    for (int i = t; i < 6 * HD / 4; i += blockDim.x)
        ((float4*)Wc)[i] = ((const float4*)W)[i];
    if (t < HD) bs[t] = b1[l * HD + t];
    __syncthreads();
    int node = blockIdx.x * 16 + (t >> 4);
    int c4 = t & 15;
    if (node >= NN) return;
    float4 acc = ((float4*)bs)[c4];
    const float* r = rbf + node * 6;
#pragma unroll
    for (int k = 0; k < 6; k++) {
        float v = r[k];
        float4 w = ((float4*)(Wc + k * HD))[c4];
        acc.x = fmaf(v, w.x, acc.x);
        acc.y = fmaf(v, w.y, acc.y);
        acc.z = fmaf(v, w.z, acc.z);
        acc.w = fmaf(v, w.w, acc.w);
    }
    ((float4*)(g_Rr3 + l * NN * HD + node * HD))[c4] = acc;
}

// ---------------- triplet stage: only active (j_idx < N) triplets ----------------
__global__ void triplet_kernel(const float* __restrict__ cbf,
                               const int* __restrict__ k_idx,
                               const int* __restrict__ j_idx,
                               const float* __restrict__ W1, int l) {
    __shared__ float Wc[6 * HD];
    int t = threadIdx.x;
    const float* W1c = W1 + l * 76 * HD + 70 * HD;
    for (int i = t; i < 6 * HD / 4; i += blockDim.x)
        ((float4*)Wc)[i] = ((const float4*)W1c)[i];
    __syncthreads();

    const float* Rr = g_Rr3 + l * NN * HD;
    int cnt = g_cnt;
    int lane = t & 15;
    int group = (blockIdx.x * blockDim.x + t) >> 4;
    int ngroups = (gridDim.x * blockDim.x) >> 4;
    for (int i = group; i < cnt; i += ngroups) {
        int tr = g_active[i];
        int k = k_idx[tr];
        int j = j_idx[tr];
        float4 a = ((const float4*)(g_Hh + k * HD))[lane];
        float4 b = ((const float4*)(Rr + j * HD))[lane];
        a.x += b.x; a.y += b.y; a.z += b.z; a.w += b.w;
        const float* cb = cbf + tr * 6;
#pragma unroll
        for (int kk = 0; kk < 6; kk++) {
            float v = cb[kk];
            float4 w = ((const float4*)(Wc + kk * HD))[lane];
            a.x = fmaf(v, w.x, a.x);
            a.y = fmaf(v, w.y, a.y);
            a.z = fmaf(v, w.z, a.z);
            a.w = fmaf(v, w.w, a.w);
        }
        a.x = fmaxf(a.x, 0.f); a.y = fmaxf(a.y, 0.f);
        a.z = fmaxf(a.z, 0.f); a.w = fmaxf(a.w, 0.f);
        red_add_v4(g_agg + j * HD + lane * 4, a);
    }
}

// ---------------- edge stage: fi = relu(P[src]+Q[dst]); scatter into aggr[dst] ----------------
__global__ void edge_kernel(const int* __restrict__ ei) {
    int t = blockIdx.x * blockDim.x + threadIdx.x;
    int lane = t & 15;
    int group = t >> 4;
    int ngroups = (gridDim.x * blockDim.x) >> 4;
    for (int e = group; e < NE; e += ngroups) {
        int s = ei[e];
        int d = ei[NE + e];
        float4 a = ((const float4*)(g_P + s * HD))[lane];
        float4 b = ((const float4*)(g_Q + d * HD))[lane];
        a.x = fmaxf(a.x + b.x, 0.f);
        a.y = fmaxf(a.y + b.y, 0.f);
        a.z = fmaxf(a.z + b.z, 0.f);
        a.w = fmaxf(a.w + b.w, 0.f);
        red_add_v4(g_aggr + d * HD + lane * 4, a);
    }
}

// ---------------- pooling ----------------
__global__ void pool_kernel(const int* __restrict__ batch) {
    int t = blockIdx.x * blockDim.x + threadIdx.x;
    int lane = t & 15;
    int n = t >> 4;
    if (n >= NN) return;
    int b = batch[n];
    float4 v = ((const float4*)(g_h + n * HD))[lane];
    red_add_v4(g_pool + b * HD + lane * 4, v);
    if (lane == 0) atomicAdd(&g_gcnt[b], 1.0f);
}

// ---------------- final small MLP ----------------
__global__ void final_kernel(const float* __restrict__ Wo1,
                             const float* __restrict__ bo1,
                             const float* __restrict__ Wo2,
                             const float* __restrict__ bo2,
                             float* __restrict__ out) {
    __shared__ float pooled[HD];
    __shared__ float t1[HD];
    int b = blockIdx.x;
    int t = threadIdx.x;  // 64 threads
    float cnt = fmaxf(g_gcnt[b], 1.0f);
    pooled[t] = fmaxf(g_pool[b * HD + t] / cnt, 0.f);
    __syncthreads();
    float acc = bo1[t];
#pragma unroll 8
    for (int k = 0; k < HD; k++) acc = fmaf(pooled[k], Wo1[k * HD + t], acc);
    t1[t] = fmaxf(acc, 0.f);
    __syncthreads();
    if (t < OUTD) {
        float a2 = bo2[t];
#pragma unroll 8
        for (int k = 0; k < HD; k++) a2 = fmaf(t1[k], Wo2[k * OUTD + t], a2);
        out[b * OUTD + t] = a2;
    }
}

// ---------------- host orchestration ----------------
extern "C" void kernel_launch(void* const* d_in, const int* in_sizes, int n_in,
                              void* d_out, int out_size) {
    (void)in_sizes; (void)n_in; (void)out_size;
    const float* x   = (const float*)d_in[0];
    const float* rbf = (const float*)d_in[1];
    const float* cbf = (const float*)d_in[2];
    const float* W1  = (const float*)d_in[3];
    const float* b1  = (const float*)d_in[4];
    const float* W2  = (const float*)d_in[5];
    const float* b2  = (const float*)d_in[6];
    const float* Wn1 = (const float*)d_in[7];
    const float* bn1 = (const float*)d_in[8];
    const float* Wn2 = (const float*)d_in[9];
    const float* bn2 = (const float*)d_in[10];
    const float* Wo1 = (const float*)d_in[11];
    const float* bo1 = (const float*)d_in[12];
    const float* Wo2 = (const float*)d_in[13];
    const float* bo2 = (const float*)d_in[14];
    const int* ei    = (const int*)d_in[15];
    const int* k_idx = (const int*)d_in[16];
    const int* j_idx = (const int*)d_in[17];
    const int* batch = (const int*)d_in[18];
    float* out = (float*)d_out;

    zero_init_kernel<<<(NN * HD / 4 + 255) / 256, 256>>>();
    compact_kernel<<<(NT + 255) / 256, 256>>>(j_idx);
    prep_weights_kernel<<<18, 256>>>(W1, W2, Wn1, Wn2);
    rbfproj_all_kernel<<<dim3(NN / 16, 3), 256>>>(rbf, W1, b1);
    proj3_mma_kernel<<<dim3(NN / 128, 3), 256>>>(x, 1, 0);

    for (int l = 0; l < 3; l++) {
        triplet_kernel<<<1024, 256>>>(cbf, k_idx, j_idx, W1, l);
        qproj_mma_kernel<<<NN / 128, 256>>>(b2 + l * HD, l);
        edge_kernel<<<4096, 256>>>(ei);
        node_update_mma_kernel<<<NN / 128, 256>>>(bn1 + l * HD, bn2 + l * HD, l);
        if (l < 2) {
            proj3_mma_kernel<<<dim3(NN / 128, 3), 256>>>(x, 0, l + 1);
        }
    }

    pool_kernel<<<(NN * 16 + 255) / 256, 256>>>(batch);
    final_kernel<<<NBATCH, 64>>>(Wo1, bo1, Wo2, bo2, out);
}